// round 15
// baseline (speedup 1.0000x reference)
#include <cuda_runtime.h>
#include <cuda_bf16.h>

// FASTMultiHeadAttention via mma.sync m16n8k16 bf16 split-precision (hi+lo).
// R15: R14 + fused finalize (last contributing CTA per (supertile, head) sums
// the slabs in fixed order and writes the normalized output; counter protocol
// with threadfence; counters self-reset for graph replays).

typedef unsigned int u32;

constexpr int Hh = 8, Nn = 2048, Dd = 64;
constexpr int NSUP = 16, MAXC = 8, THREADS = 512;
constexpr int MST = 36;    // u32 row stride bf16x2 tiles
constexpr int QST = 80;    // QRS stride (floats, even)
constexpr int OST = 66;    // Ored stride

// smem u32 offsets
constexpr int O_QH = 0,     O_QL = 4608;    // Q [128][36] x2
constexpr int O_KH = 9216,  O_KL = 11520;   // K [64][36] x2
constexpr int O_RH = 13824, O_RL = 27648;   // R [384][36] x2 (chunk-persistent)
constexpr int O_VTH = 41472, O_VTL = 43776; // V^T [64][36] x2
constexpr int O_QRS = 46080;                // [128][80] f32 (Ored [128][66] overlay)
constexpr int O_DN = 56320;                 // [128][8] f32 (inv[128] + flag overlay)
constexpr int SMEMF = 57344;                // 229376 B

__device__ float g_Opart[(size_t)MAXC * Hh * Nn * Dd];   // 33.5 MB
__device__ float g_dpart[MAXC * Hh * Nn];
__device__ unsigned g_cnt[NSUP * Hh];                    // zero-init; self-reset

__device__ __forceinline__ void split2(float a, float b, u32& hi, u32& lo) {
    __nv_bfloat162 h = __floats2bfloat162_rn(a, b);
    float ra = a - __bfloat162float(h.x);
    float rb = b - __bfloat162float(h.y);
    __nv_bfloat162 l = __floats2bfloat162_rn(ra, rb);
    hi = *(u32*)&h; lo = *(u32*)&l;
}
__device__ __forceinline__ void mma16(float* c, const u32* a, const u32* b) {
    asm volatile("mma.sync.aligned.m16n8k16.row.col.f32.bf16.bf16.f32 "
        "{%0,%1,%2,%3},{%4,%5,%6,%7},{%8,%9},{%0,%1,%2,%3};"
        : "+f"(c[0]), "+f"(c[1]), "+f"(c[2]), "+f"(c[3])
        : "r"(a[0]), "r"(a[1]), "r"(a[2]), "r"(a[3]), "r"(b[0]), "r"(b[1]));
}
__device__ __forceinline__ void ldA(const u32* M, int r0, int g, int t, u32* a) {
    #pragma unroll
    for (int kc = 0; kc < 4; ++kc) {
        a[kc*4+0] = M[(r0 + g)     * MST + kc*8 + t];
        a[kc*4+1] = M[(r0 + g + 8) * MST + kc*8 + t];
        a[kc*4+2] = M[(r0 + g)     * MST + kc*8 + t + 4];
        a[kc*4+3] = M[(r0 + g + 8) * MST + kc*8 + t + 4];
    }
}
__device__ __forceinline__ void gemmB(const u32* BH, const u32* BL, int n0, float* c,
                                      const u32* aH, const u32* aL, int g, int t) {
    #pragma unroll
    for (int kc = 0; kc < 4; ++kc) {
        u32 bh[2], bl[2];
        int base = (n0 + g) * MST + kc*8 + t;
        bh[0] = BH[base]; bh[1] = BH[base + 4];
        bl[0] = BL[base]; bl[1] = BL[base + 4];
        mma16(c, aH + kc*4, bh);
        mma16(c, aH + kc*4, bl);
        mma16(c, aL + kc*4, bh);
    }
}
__device__ __forceinline__ void gemmO(const u32* BH, const u32* BL, int n0, float* c,
                                      const u32* aH, const u32* aL, int g, int t, int jb) {
    #pragma unroll
    for (int kc = 0; kc < 2; ++kc) {
        u32 bh[2], bl[2];
        int base = (n0 + g) * MST + jb + kc*8 + t;
        bh[0] = BH[base]; bh[1] = BH[base + 4];
        bl[0] = BL[base]; bl[1] = BL[base + 4];
        mma16(c, aH + kc*4, bh);
        mma16(c, aH + kc*4, bl);
        mma16(c, aL + kc*4, bh);
    }
}

__global__ __launch_bounds__(THREADS, 1)
void fastmax_mma(const float* __restrict__ q, const float* __restrict__ kg,
                 const float* __restrict__ vg, const float* __restrict__ rpe,
                 const int* __restrict__ maskp, float* __restrict__ out)
{
    extern __shared__ u32 smU[];
    float* QRS = (float*)(smU + O_QRS);
    float* dnS = (float*)(smU + O_DN);

    const int bx = blockIdx.x;
    const int ts = NSUP - 1 - (bx >> 6);        // supertile, heavy-first
    const int rem = bx & 63;
    const int cs = rem >> 3, h = rem & 7;       // cs in [0,7]

    const bool causal = maskp ? (maskp[0] != 0) : true;
    if (causal && cs > (ts >> 1)) return;
    const int i0 = ts * 128;
    int nsteps = 4;
    if (causal) { int v = 2 * (ts - 2 * cs) + 2; nsteps = v < 4 ? v : 4; }
    const int nch = causal ? ((ts >> 1) + 1) : MAXC;
    const int rel0 = 128 * ts - 256 * cs + 1792;   // band window base

    const int tid = threadIdx.x;
    const int w = tid >> 5, lane = tid & 31;
    const int g = lane >> 2, t = lane & 3;
    const int rb = w >> 1, half = w & 1;

    const float* qh = q  + (size_t)h * Nn * Dd;
    const float* kh = kg + (size_t)h * Nn * Dd;
    const float* vh = vg + (size_t)h * Nn * Dd;

    // ---- stage Q [128x64] hi/lo ----
    #pragma unroll
    for (int u = 0; u < 4; ++u) {
        int idx = tid + u * THREADS, r = idx >> 4, c4 = (idx & 15) * 4;
        float4 v = *(const float4*)(qh + (size_t)(i0 + r) * Dd + c4);
        u32 h0, l0, h1, l1; split2(v.x, v.y, h0, l0); split2(v.z, v.w, h1, l1);
        int kp = c4 >> 1;
        *(uint2*)(smU + O_QH + r * MST + kp) = make_uint2(h0, h1);
        *(uint2*)(smU + O_QL + r * MST + kp) = make_uint2(l0, l1);
    }
    // ---- stage R band [383x64] once per CTA (+zero row 383) ----
    #pragma unroll
    for (int u = 0; u < 12; ++u) {
        int idx = tid + u * THREADS;
        if (idx < 383 * 16) {
            int r = idx >> 4, c4 = (idx & 15) * 4;
            float4 v = *(const float4*)(rpe + (size_t)(rel0 + r) * Dd + c4);
            u32 h0, l0, h1, l1; split2(v.x, v.y, h0, l0); split2(v.z, v.w, h1, l1);
            int kp = c4 >> 1;
            *(uint2*)(smU + O_RH + r * MST + kp) = make_uint2(h0, h1);
            *(uint2*)(smU + O_RL + r * MST + kp) = make_uint2(l0, l1);
        }
    }
    if (tid < 36) {
        smU[O_RH + 383 * MST + tid] = 0;
        smU[O_RL + 383 * MST + tid] = 0;
    }
    __syncthreads();

    u32 aQH[16], aQL[16];
    ldA(smU + O_QH, rb * 16, g, t, aQH);
    ldA(smU + O_QL, rb * 16, g, t, aQL);

    float oc[8][4] = {};
    float dnacc[2] = {0.f, 0.f};

    for (int tl = 0; tl < nsteps; ++tl) {
        const int j0 = cs * 256 + tl * 64;
        const int jrel = j0 - i0;               // multiple of 64; mask only if >= 0
        const bool doMask = causal && (jrel >= 0);
        const int roff = 192 - 64 * tl;

        // ---- stage K hi/lo (overlaps prior O-GEMM; disjoint regions) ----
        #pragma unroll
        for (int u = 0; u < 2; ++u) {
            int idx = tid + u * THREADS, r = idx >> 4, c4 = (idx & 15) * 4;
            float4 v = *(const float4*)(kh + (size_t)(j0 + r) * Dd + c4);
            u32 h0, l0, h1, l1; split2(v.x, v.y, h0, l0); split2(v.z, v.w, h1, l1);
            int kp = c4 >> 1;
            *(uint2*)(smU + O_KH + r * MST + kp) = make_uint2(h0, h1);
            *(uint2*)(smU + O_KL + r * MST + kp) = make_uint2(l0, l1);
        }
        __syncthreads();                       // K ready; prior O-GEMM done

        // ---- S1 = Q K^T ----
        float s1c[4][4] = {};
        #pragma unroll
        for (int ci = 0; ci < 4; ++ci)
            gemmB(smU + O_KH, smU + O_KL, (half * 4 + ci) * 8, s1c[ci], aQH, aQL, g, t);
        // ---- QR = Q R^T, bands [16rb, 16rb+79], row offset roff ----
        #pragma unroll
        for (int qi = 0; qi < 5; ++qi) {
            int cb = 2 * rb + half * 5 + qi;
            float qc[4] = {};
            gemmB(smU + O_RH, smU + O_RL, cb * 8 + roff, qc, aQH, aQL, g, t);
            int rI = rb * 16 + g;
            int jb = 8 * (half * 5 + qi) + 2 * t;
            *(float2*)(QRS + rI * QST + jb)       = make_float2(qc[0], qc[1]);
            *(float2*)(QRS + (rI + 8) * QST + jb) = make_float2(qc[2], qc[3]);
        }
        __syncthreads();                       // QRS ready; K/R frag reads done

        // ---- epilogue: w in regs -> A-frags; dn; mask ----
        u32 aWH[8], aWL[8];
        #pragma unroll
        for (int ci = 0; ci < 4; ++ci) {
            int colA = (half * 4 + ci) * 8 + 2 * t;
            float wv[4];
            #pragma unroll
            for (int pr = 0; pr < 2; ++pr) {
                int row = rb * 16 + g + pr * 8;
                int jb  = g + pr * 8 - colA + 63;
                float sA = s1c[ci][pr*2+0] + QRS[row * QST + jb];
                float sB = s1c[ci][pr*2+1] + QRS[row * QST + jb - 1];
                float wA = fmaf(0.5f * sA, sA, 1.0f + sA);
                float wB = fmaf(0.5f * sB, sB, 1.0f + sB);
                if (doMask) {
                    if (jrel + colA     > row) wA = 0.0f;
                    if (jrel + colA + 1 > row) wB = 0.0f;
                }
                dnacc[pr] += wA + wB;
                wv[pr*2+0] = wA; wv[pr*2+1] = wB;
            }
            int ai = (ci >> 1) * 4 + (ci & 1) * 2;
            split2(wv[0], wv[1], aWH[ai],     aWL[ai]);
            split2(wv[2], wv[3], aWH[ai + 1], aWL[ai + 1]);
        }
        // ---- stage V^T hi/lo ----
        {
            __nv_bfloat16* VtH = (__nv_bfloat16*)(smU + O_VTH);
            __nv_bfloat16* VtL = (__nv_bfloat16*)(smU + O_VTL);
            #pragma unroll
            for (int u = 0; u < 2; ++u) {
                int idx = tid + u * THREADS, jj = idx >> 4, d4 = (idx & 15) * 4;
                float4 v = *(const float4*)(vh + (size_t)(j0 + jj) * Dd + d4);
                float vv[4] = {v.x, v.y, v.z, v.w};
                #pragma unroll
                for (int dd = 0; dd < 4; ++dd) {
                    __nv_bfloat16 hb = __float2bfloat16_rn(vv[dd]);
                    __nv_bfloat16 lb = __float2bfloat16_rn(vv[dd] - __bfloat162float(hb));
                    int bi = ((d4 + dd) * MST + (jj >> 1)) * 2 + (jj & 1);
                    VtH[bi] = hb; VtL[bi] = lb;
                }
            }
        }
        __syncthreads();                       // Vt ready; QRS reads done

        // ---- O += W(regs) x V over warp's j-half, all 8 d-blocks ----
        #pragma unroll
        for (int cb = 0; cb < 8; ++cb)
            gemmO(smU + O_VTH, smU + O_VTL, cb * 8, oc[cb], aWH, aWL, g, t, half * 16);
    }

    // ---- cross-half O reduce + denom + slab writes ----
    dnS[(rb * 16 + g) * 8 + half * 4 + t]     = dnacc[0];
    dnS[(rb * 16 + g + 8) * 8 + half * 4 + t] = dnacc[1];
    float* Ored = (float*)(smU + O_QRS);       // [128][66] overlay
    if (half == 1) {
        #pragma unroll
        for (int cb = 0; cb < 8; ++cb) {
            *(float2*)(Ored + (rb*16 + g) * OST + cb*8 + 2*t)     = make_float2(oc[cb][0], oc[cb][1]);
            *(float2*)(Ored + (rb*16 + g + 8) * OST + cb*8 + 2*t) = make_float2(oc[cb][2], oc[cb][3]);
        }
    }
    __syncthreads();

    const size_t slabO = ((size_t)(cs * Hh + h)) * Nn * Dd;
    if (half == 0) {
        #pragma unroll
        for (int cb = 0; cb < 8; ++cb) {
            float2 r0 = *(float2*)(Ored + (rb*16 + g) * OST + cb*8 + 2*t);
            float2 r1 = *(float2*)(Ored + (rb*16 + g + 8) * OST + cb*8 + 2*t);
            *(float2*)(g_Opart + slabO + (size_t)(i0 + rb*16 + g) * Dd + cb*8 + 2*t) =
                make_float2(oc[cb][0] + r0.x, oc[cb][1] + r0.y);
            *(float2*)(g_Opart + slabO + (size_t)(i0 + rb*16 + g + 8) * Dd + cb*8 + 2*t) =
                make_float2(oc[cb][2] + r1.x, oc[cb][3] + r1.y);
        }
    }
    if (tid < 128) {
        float s = 0.f;
        #pragma unroll
        for (int k2 = 0; k2 < 8; ++k2) s += dnS[tid * 8 + k2];
        g_dpart[((size_t)(cs * Hh + h)) * Nn + i0 + tid] = s;
    }

    // ---- fused finalize: last contributing CTA for (ts, h) reduces slabs ----
    __threadfence();                           // release our slab/dpart writes
    __syncthreads();                           // all threads fenced; smem reads done
    if (tid == 0)
        smU[O_DN + 512] = atomicAdd(&g_cnt[ts * Hh + h], 1u);
    __syncthreads();
    if (smU[O_DN + 512] == (unsigned)(nch - 1)) {
        __threadfence();                       // acquire peers' slab/dpart writes
        float* inv = (float*)(smU + O_DN);     // [128]
        if (tid < 128) {
            float ds = 0.f;
            for (int cc = 0; cc < nch; ++cc)
                ds += g_dpart[((size_t)(cc * Hh + h)) * Nn + i0 + tid];
            inv[tid] = 1.0f / ds;
        }
        __syncthreads();
        #pragma unroll
        for (int u = 0; u < 4; ++u) {
            int idx = tid + u * THREADS, r = idx >> 4, c4 = (idx & 15) * 4;
            const size_t boff = (size_t)(i0 + r) * Dd + c4;
            float4 osum = make_float4(0.f, 0.f, 0.f, 0.f);
            for (int cc = 0; cc < nch; ++cc) {
                float4 p = *(const float4*)(g_Opart + ((size_t)(cc * Hh + h)) * Nn * Dd + boff);
                osum.x += p.x; osum.y += p.y; osum.z += p.z; osum.w += p.w;
            }
            float iv = inv[r];
            *(float4*)(out + (size_t)h * Nn * Dd + boff) =
                make_float4(osum.x * iv, osum.y * iv, osum.z * iv, osum.w * iv);
        }
        if (tid == 0) g_cnt[ts * Hh + h] = 0;  // reset for next launch/replay
    }
}

extern "C" void kernel_launch(void* const* d_in, const int* in_sizes, int n_in,
                              void* d_out, int out_size)
{
    const float* q   = (const float*)d_in[0];
    const float* k   = (const float*)d_in[1];
    const float* v   = (const float*)d_in[2];
    const float* rpe = (const float*)d_in[3];
    const int*   msk = (n_in >= 5) ? (const int*)d_in[4] : nullptr;
    float* out = (float*)d_out;

    const size_t smem = (size_t)SMEMF * sizeof(u32);   // 229376 B
    cudaFuncSetAttribute(fastmax_mma, cudaFuncAttributeMaxDynamicSharedMemorySize, (int)smem);
    fastmax_mma<<<NSUP * MAXC * Hh, THREADS, smem>>>(q, k, v, rpe, msk, out);
}

// round 16
// speedup vs baseline: 1.6865x; 1.6865x over previous
#include <cuda_runtime.h>
#include <cuda_fp16.h>

// FASTMultiHeadAttention via mma.sync m16n8k16 fp16 (single precision-level).
// R16 = R14 structure (256-col chunks, 4 steps/CTA, separate finalize) with
// the bf16 hi/lo split collapsed to single fp16: 1 MMA (not 3) per k-chunk,
// half the fragment LDS, half the staging. Error anchor: measured 6.8e-6 with
// split-bf16 -> x37 for fp16-single -> ~2.5e-4, under the 1e-3 threshold.

typedef unsigned int u32;

constexpr int Hh = 8, Nn = 2048, Dd = 64;
constexpr int NSUP = 16, MAXC = 8, THREADS = 512;
constexpr int MST = 36;    // u32 row stride fp16x2 tiles (bank=4g+t pattern, conflict-free)
constexpr int QST = 80;    // QRS stride (floats, even)
constexpr int OST = 66;    // Ored stride

// smem u32 offsets
constexpr int O_Q   = 0;       // Q  [128][36]
constexpr int O_K   = 4608;    // K  [64][36]
constexpr int O_R   = 6912;    // R  [384][36] (chunk-persistent)
constexpr int O_VT  = 20736;   // V^T [64][36]
constexpr int O_QRS = 23040;   // [128][80] f32 (Ored [128][66] overlay)
constexpr int O_DN  = 33280;   // [128][8] f32
constexpr int SMEMF = 34304;   // 137216 B

__device__ float g_Opart[(size_t)MAXC * Hh * Nn * Dd];   // 33.5 MB
__device__ float g_dpart[MAXC * Hh * Nn];

__device__ __forceinline__ u32 h2pack(float a, float b) {
    __half2 h = __floats2half2_rn(a, b);
    return *(u32*)&h;
}
__device__ __forceinline__ void mma16(float* c, const u32* a, const u32* b) {
    asm volatile("mma.sync.aligned.m16n8k16.row.col.f32.f16.f16.f32 "
        "{%0,%1,%2,%3},{%4,%5,%6,%7},{%8,%9},{%0,%1,%2,%3};"
        : "+f"(c[0]), "+f"(c[1]), "+f"(c[2]), "+f"(c[3])
        : "r"(a[0]), "r"(a[1]), "r"(a[2]), "r"(a[3]), "r"(b[0]), "r"(b[1]));
}
// A fragments: 16 rows at r0, K=64 -> 4 chunks x 4 regs
__device__ __forceinline__ void ldA(const u32* M, int r0, int g, int t, u32* a) {
    #pragma unroll
    for (int kc = 0; kc < 4; ++kc) {
        a[kc*4+0] = M[(r0 + g)     * MST + kc*8 + t];
        a[kc*4+1] = M[(r0 + g + 8) * MST + kc*8 + t];
        a[kc*4+2] = M[(r0 + g)     * MST + kc*8 + t + 4];
        a[kc*4+3] = M[(r0 + g + 8) * MST + kc*8 + t + 4];
    }
}
// C += A x B^T over K=64; B stored [n][k-pairs]
__device__ __forceinline__ void gemmB(const u32* B, int n0, float* c,
                                      const u32* a, int g, int t) {
    #pragma unroll
    for (int kc = 0; kc < 4; ++kc) {
        u32 b[2];
        int base = (n0 + g) * MST + kc*8 + t;
        b[0] = B[base]; b[1] = B[base + 4];
        mma16(c, a + kc*4, b);
    }
}
// O GEMM: K=32 (warp's j-half), jb = k-pair base offset (half*16)
__device__ __forceinline__ void gemmO(const u32* B, int n0, float* c,
                                      const u32* a, int g, int t, int jb) {
    #pragma unroll
    for (int kc = 0; kc < 2; ++kc) {
        u32 b[2];
        int base = (n0 + g) * MST + jb + kc*8 + t;
        b[0] = B[base]; b[1] = B[base + 4];
        mma16(c, a + kc*4, b);
    }
}

__global__ __launch_bounds__(THREADS, 1)
void fastmax_mma(const float* __restrict__ q, const float* __restrict__ kg,
                 const float* __restrict__ vg, const float* __restrict__ rpe,
                 const int* __restrict__ maskp)
{
    extern __shared__ u32 smU[];
    float* QRS = (float*)(smU + O_QRS);
    float* dnS = (float*)(smU + O_DN);

    const int bx = blockIdx.x;
    const int ts = NSUP - 1 - (bx >> 6);        // supertile, heavy-first
    const int rem = bx & 63;
    const int cs = rem >> 3, h = rem & 7;       // cs in [0,7]

    const bool causal = maskp ? (maskp[0] != 0) : true;
    if (causal && cs > (ts >> 1)) return;
    const int i0 = ts * 128;
    int nsteps = 4;
    if (causal) { int v = 2 * (ts - 2 * cs) + 2; nsteps = v < 4 ? v : 4; }
    const int rel0 = 128 * ts - 256 * cs + 1792;   // band window base

    const int tid = threadIdx.x;
    const int w = tid >> 5, lane = tid & 31;
    const int g = lane >> 2, t = lane & 3;
    const int rb = w >> 1, half = w & 1;

    const float* qh = q  + (size_t)h * Nn * Dd;
    const float* kh = kg + (size_t)h * Nn * Dd;
    const float* vh = vg + (size_t)h * Nn * Dd;

    // ---- stage Q [128x64] fp16 ----
    #pragma unroll
    for (int u = 0; u < 4; ++u) {
        int idx = tid + u * THREADS, r = idx >> 4, c4 = (idx & 15) * 4;
        float4 v = *(const float4*)(qh + (size_t)(i0 + r) * Dd + c4);
        *(uint2*)(smU + O_Q + r * MST + (c4 >> 1)) =
            make_uint2(h2pack(v.x, v.y), h2pack(v.z, v.w));
    }
    // ---- stage R band [383x64] once per CTA (+zero row 383) ----
    #pragma unroll
    for (int u = 0; u < 12; ++u) {
        int idx = tid + u * THREADS;
        if (idx < 383 * 16) {
            int r = idx >> 4, c4 = (idx & 15) * 4;
            float4 v = *(const float4*)(rpe + (size_t)(rel0 + r) * Dd + c4);
            *(uint2*)(smU + O_R + r * MST + (c4 >> 1)) =
                make_uint2(h2pack(v.x, v.y), h2pack(v.z, v.w));
        }
    }
    if (tid < 36) smU[O_R + 383 * MST + tid] = 0;
    __syncthreads();

    u32 aQ[16];
    ldA(smU + O_Q, rb * 16, g, t, aQ);

    float oc[8][4] = {};
    float dnacc[2] = {0.f, 0.f};

    for (int tl = 0; tl < nsteps; ++tl) {
        const int j0 = cs * 256 + tl * 64;
        const int jrel = j0 - i0;               // multiple of 64; mask only if >= 0
        const bool doMask = causal && (jrel >= 0);
        const int roff = 192 - 64 * tl;

        // ---- stage K fp16 (overlaps prior O-GEMM; disjoint regions) ----
        #pragma unroll
        for (int u = 0; u < 2; ++u) {
            int idx = tid + u * THREADS, r = idx >> 4, c4 = (idx & 15) * 4;
            float4 v = *(const float4*)(kh + (size_t)(j0 + r) * Dd + c4);
            *(uint2*)(smU + O_K + r * MST + (c4 >> 1)) =
                make_uint2(h2pack(v.x, v.y), h2pack(v.z, v.w));
        }
        __syncthreads();                       // K ready; prior O-GEMM done

        // ---- S1 = Q K^T ----
        float s1c[4][4] = {};
        #pragma unroll
        for (int ci = 0; ci < 4; ++ci)
            gemmB(smU + O_K, (half * 4 + ci) * 8, s1c[ci], aQ, g, t);
        // ---- QR = Q R^T, bands [16rb, 16rb+79], row offset roff ----
        #pragma unroll
        for (int qi = 0; qi < 5; ++qi) {
            int cb = 2 * rb + half * 5 + qi;
            float qc[4] = {};
            gemmB(smU + O_R, cb * 8 + roff, qc, aQ, g, t);
            int rI = rb * 16 + g;
            int jb = 8 * (half * 5 + qi) + 2 * t;
            *(float2*)(QRS + rI * QST + jb)       = make_float2(qc[0], qc[1]);
            *(float2*)(QRS + (rI + 8) * QST + jb) = make_float2(qc[2], qc[3]);
        }
        __syncthreads();                       // QRS ready; K/R frag reads done

        // ---- epilogue: w in regs -> fp16 A-frags; dn; mask ----
        u32 aW[8];
        #pragma unroll
        for (int ci = 0; ci < 4; ++ci) {
            int colA = (half * 4 + ci) * 8 + 2 * t;
            float wv[4];
            #pragma unroll
            for (int pr = 0; pr < 2; ++pr) {
                int row = rb * 16 + g + pr * 8;
                int jb  = g + pr * 8 - colA + 63;
                float sA = s1c[ci][pr*2+0] + QRS[row * QST + jb];
                float sB = s1c[ci][pr*2+1] + QRS[row * QST + jb - 1];
                float wA = fmaf(0.5f * sA, sA, 1.0f + sA);
                float wB = fmaf(0.5f * sB, sB, 1.0f + sB);
                if (doMask) {
                    if (jrel + colA     > row) wA = 0.0f;
                    if (jrel + colA + 1 > row) wB = 0.0f;
                }
                dnacc[pr] += wA + wB;
                wv[pr*2+0] = wA; wv[pr*2+1] = wB;
            }
            int ai = (ci >> 1) * 4 + (ci & 1) * 2;
            aW[ai]     = h2pack(wv[0], wv[1]);
            aW[ai + 1] = h2pack(wv[2], wv[3]);
        }
        // ---- stage V^T fp16 ----
        {
            __half* Vt = (__half*)(smU + O_VT);
            #pragma unroll
            for (int u = 0; u < 2; ++u) {
                int idx = tid + u * THREADS, jj = idx >> 4, d4 = (idx & 15) * 4;
                float4 v = *(const float4*)(vh + (size_t)(j0 + jj) * Dd + d4);
                float vv[4] = {v.x, v.y, v.z, v.w};
                #pragma unroll
                for (int dd = 0; dd < 4; ++dd) {
                    int bi = ((d4 + dd) * MST + (jj >> 1)) * 2 + (jj & 1);
                    Vt[bi] = __float2half_rn(vv[dd]);
                }
            }
        }
        __syncthreads();                       // Vt ready; QRS reads done

        // ---- O += W(regs) x V over warp's j-half, all 8 d-blocks ----
        #pragma unroll
        for (int cb = 0; cb < 8; ++cb)
            gemmO(smU + O_VT, cb * 8, oc[cb], aW, g, t, half * 16);
    }

    // ---- cross-half O reduce + denom + slab writes ----
    dnS[(rb * 16 + g) * 8 + half * 4 + t]     = dnacc[0];
    dnS[(rb * 16 + g + 8) * 8 + half * 4 + t] = dnacc[1];
    float* Ored = (float*)(smU + O_QRS);       // [128][66] overlay
    if (half == 1) {
        #pragma unroll
        for (int cb = 0; cb < 8; ++cb) {
            *(float2*)(Ored + (rb*16 + g) * OST + cb*8 + 2*t)     = make_float2(oc[cb][0], oc[cb][1]);
            *(float2*)(Ored + (rb*16 + g + 8) * OST + cb*8 + 2*t) = make_float2(oc[cb][2], oc[cb][3]);
        }
    }
    __syncthreads();

    const size_t slabO = ((size_t)(cs * Hh + h)) * Nn * Dd;
    if (half == 0) {
        #pragma unroll
        for (int cb = 0; cb < 8; ++cb) {
            float2 r0 = *(float2*)(Ored + (rb*16 + g) * OST + cb*8 + 2*t);
            float2 r1 = *(float2*)(Ored + (rb*16 + g + 8) * OST + cb*8 + 2*t);
            *(float2*)(g_Opart + slabO + (size_t)(i0 + rb*16 + g) * Dd + cb*8 + 2*t) =
                make_float2(oc[cb][0] + r0.x, oc[cb][1] + r0.y);
            *(float2*)(g_Opart + slabO + (size_t)(i0 + rb*16 + g + 8) * Dd + cb*8 + 2*t) =
                make_float2(oc[cb][2] + r1.x, oc[cb][3] + r1.y);
        }
    }
    if (tid < 128) {
        float s = 0.f;
        #pragma unroll
        for (int k2 = 0; k2 < 8; ++k2) s += dnS[tid * 8 + k2];
        g_dpart[((size_t)(cs * Hh + h)) * Nn + i0 + tid] = s;
    }
}

__global__ void finalize_kernel(const int* __restrict__ maskp, float* __restrict__ out)
{
    const bool causal = maskp ? (maskp[0] != 0) : true;
    int base = (blockIdx.x * blockDim.x + threadIdx.x) * 4;
    if (base >= Hh * Nn * Dd) return;
    const int h = base >> 17;
    const int i = (base >> 6) & (Nn - 1);
    const int nc = causal ? ((i >> 8) + 1) : MAXC;   // active 256-col chunks
    const int boff = base - h * (Nn * Dd);

    float dsum = 0.0f;
    float4 osum = make_float4(0.f, 0.f, 0.f, 0.f);
    for (int cc = 0; cc < nc; ++cc) {
        size_t s = (size_t)(cc * Hh + h);
        dsum += g_dpart[s * Nn + i];
        float4 p = *(const float4*)(g_Opart + s * Nn * Dd + boff);
        osum.x += p.x; osum.y += p.y; osum.z += p.z; osum.w += p.w;
    }
    float inv = 1.0f / dsum;
    *(float4*)(out + base) = make_float4(osum.x * inv, osum.y * inv, osum.z * inv, osum.w * inv);
}

extern "C" void kernel_launch(void* const* d_in, const int* in_sizes, int n_in,
                              void* d_out, int out_size)
{
    const float* q   = (const float*)d_in[0];
    const float* k   = (const float*)d_in[1];
    const float* v   = (const float*)d_in[2];
    const float* rpe = (const float*)d_in[3];
    const int*   msk = (n_in >= 5) ? (const int*)d_in[4] : nullptr;
    float* out = (float*)d_out;

    const size_t smem = (size_t)SMEMF * sizeof(u32);   // 137216 B
    cudaFuncSetAttribute(fastmax_mma, cudaFuncAttributeMaxDynamicSharedMemorySize, (int)smem);
    fastmax_mma<<<NSUP * MAXC * Hh, THREADS, smem>>>(q, k, v, rpe, msk);
    finalize_kernel<<<(Hh * Nn * Dd / 4) / 256, 256>>>(msk, out);
}